// round 1
// baseline (speedup 1.0000x reference)
#include <cuda_runtime.h>
#include <math_constants.h>

#define SEQ  2048
#define ROWS 4096      // B*S = 2*2048
#define DIM  4096
#define NH   32
#define NKV  8
#define HD   128
#define KVDIM 1024

// -------- scratch (no allocations allowed; __device__ globals) --------
__device__ float g_q[ROWS * NH * HD];      // 64 MB
__device__ float g_k[ROWS * NKV * HD];     // 16 MB
__device__ float g_v[ROWS * NKV * HD];     // 16 MB
__device__ float g_attn[ROWS * NH * HD];   // 64 MB

// ======================================================================
// GEMM: C[M,N] = A[M,K] * B[N,K]^T   (both A and B are K-contiguous)
// Tiles: BM=128, BN=64, BK=16, 256 threads, 8x4 register micro-tile.
// ======================================================================
__global__ __launch_bounds__(256) void gemm_tn(
    const float* __restrict__ A, const float* __restrict__ B,
    float* __restrict__ C, int M, int N, int K)
{
    __shared__ float As[16 * 132];   // [k][m], padded stride 132
    __shared__ float Bs[16 * 68];    // [k][n], padded stride 68

    const int tid = threadIdx.x;
    const int m0 = blockIdx.y * 128;
    const int n0 = blockIdx.x * 64;
    const int ty = tid >> 4;   // 0..15 -> rows 8*ty..
    const int tx = tid & 15;   // 0..15 -> cols 4*tx..

    float acc[8][4];
#pragma unroll
    for (int i = 0; i < 8; i++)
#pragma unroll
        for (int j = 0; j < 4; j++) acc[i][j] = 0.f;

    for (int k0 = 0; k0 < K; k0 += 16) {
        __syncthreads();
        // A tile: 128 rows x 16 k = 512 float4 loads (transposed store)
#pragma unroll
        for (int it = 0; it < 2; it++) {
            int i  = tid + it * 256;
            int mm = i >> 2, kc = i & 3;
            float4 va = *(const float4*)(A + (size_t)(m0 + mm) * K + k0 + 4 * kc);
            As[(4 * kc + 0) * 132 + mm] = va.x;
            As[(4 * kc + 1) * 132 + mm] = va.y;
            As[(4 * kc + 2) * 132 + mm] = va.z;
            As[(4 * kc + 3) * 132 + mm] = va.w;
        }
        // B tile: 64 rows x 16 k = 256 float4 loads
        {
            int nn = tid >> 2, kc = tid & 3;
            float4 vb = *(const float4*)(B + (size_t)(n0 + nn) * K + k0 + 4 * kc);
            Bs[(4 * kc + 0) * 68 + nn] = vb.x;
            Bs[(4 * kc + 1) * 68 + nn] = vb.y;
            Bs[(4 * kc + 2) * 68 + nn] = vb.z;
            Bs[(4 * kc + 3) * 68 + nn] = vb.w;
        }
        __syncthreads();

#pragma unroll
        for (int k = 0; k < 16; k++) {
            float4 a0 = *(const float4*)(As + k * 132 + 8 * ty);
            float4 a1 = *(const float4*)(As + k * 132 + 8 * ty + 4);
            float4 b0 = *(const float4*)(Bs + k * 68 + 4 * tx);
            float a[8] = {a0.x, a0.y, a0.z, a0.w, a1.x, a1.y, a1.z, a1.w};
            float b[4] = {b0.x, b0.y, b0.z, b0.w};
#pragma unroll
            for (int i = 0; i < 8; i++)
#pragma unroll
                for (int j = 0; j < 4; j++)
                    acc[i][j] += a[i] * b[j];
        }
    }

#pragma unroll
    for (int i = 0; i < 8; i++) {
        float4 o = make_float4(acc[i][0], acc[i][1], acc[i][2], acc[i][3]);
        *(float4*)(C + (size_t)(m0 + 8 * ty + i) * N + n0 + 4 * tx) = o;
    }
}

// ======================================================================
// RoPE (interleaved pairs), t layout [row, head, 128], row = b*SEQ + s
// ======================================================================
__global__ void rope_kernel(float* __restrict__ t, const float* __restrict__ cs,
                            const float* __restrict__ sn, int nheads)
{
    int idx = blockIdx.x * blockDim.x + threadIdx.x;
    int total = ROWS * nheads * 64;
    if (idx >= total) return;
    int i   = idx & 63;
    int hh  = (idx >> 6) % nheads;
    int row = idx / (64 * nheads);
    int s   = row & (SEQ - 1);
    float c = cs[s * 64 + i];
    float sv = sn[s * 64 + i];
    float2* p = (float2*)(t + ((size_t)row * nheads + hh) * HD) + i;
    float2 v = *p;
    *p = make_float2(v.x * c - v.y * sv, v.x * sv + v.y * c);
}

// ======================================================================
// Flash attention, causal, GQA (4 Q heads per KV head), fp32.
// Block: 128 threads handles 64 queries for one (b, h).
// Per thread: scores micro-tile 4 rows x 8 cols; O micro-tile 4 rows x 16 cols.
// ======================================================================
#define QS_STR 130
#define KS_STR 130
#define VS_STR 132
#define SS_STR 66
#define ATTN_SMEM ((64 * QS_STR + 64 * KS_STR + 64 * VS_STR + 64 * SS_STR) * 4)

__global__ __launch_bounds__(128) void attn_kernel(
    const float* __restrict__ q, const float* __restrict__ k,
    const float* __restrict__ v, float* __restrict__ o)
{
    extern __shared__ float sm[];
    float* Qs = sm;                     // 64 x 128 (stride 130)
    float* Ks = Qs + 64 * QS_STR;       // 64 x 128 (stride 130)
    float* Vs = Ks + 64 * KS_STR;       // 64 x 128 (stride 132)
    float* Ss = Vs + 64 * VS_STR;       // 64 x 64  (stride 66)

    const int qb = blockIdx.x;          // 0..31
    const int h  = blockIdx.y;          // 0..31
    const int b  = blockIdx.z;          // 0..1
    const int kvh = h >> 2;
    const int tid = threadIdx.x;
    const int ty = tid >> 3;            // 0..15 -> rows 4*ty..
    const int tx = tid & 7;             // 0..7

    // Load Q tile (64 x 128), float4 granularity
#pragma unroll
    for (int it = 0; it < 16; it++) {
        int i = tid + it * 128;         // 0..2047 float4s
        int rr = i >> 5, d4 = i & 31;
        float4 vq = *(const float4*)(q + ((size_t)((b * SEQ + qb * 64 + rr) * NH + h)) * HD + 4 * d4);
        Qs[rr * QS_STR + 4 * d4 + 0] = vq.x;
        Qs[rr * QS_STR + 4 * d4 + 1] = vq.y;
        Qs[rr * QS_STR + 4 * d4 + 2] = vq.z;
        Qs[rr * QS_STR + 4 * d4 + 3] = vq.w;
    }

    float acc[4][16];
#pragma unroll
    for (int i = 0; i < 4; i++)
#pragma unroll
        for (int c = 0; c < 16; c++) acc[i][c] = 0.f;
    float m_i[4], l_i[4];
#pragma unroll
    for (int i = 0; i < 4; i++) { m_i[i] = -CUDART_INF_F; l_i[i] = 0.f; }

    const float scale = 0.088388347648318447f;   // 1/sqrt(128)

    for (int kb = 0; kb <= qb; kb++) {
        __syncthreads();
        // Load K and V tiles for this key block
#pragma unroll
        for (int it = 0; it < 16; it++) {
            int i = tid + it * 128;
            int rr = i >> 5, d4 = i & 31;
            size_t base = ((size_t)((b * SEQ + kb * 64 + rr) * NKV + kvh)) * HD + 4 * d4;
            float4 vk = *(const float4*)(k + base);
            Ks[rr * KS_STR + 4 * d4 + 0] = vk.x;
            Ks[rr * KS_STR + 4 * d4 + 1] = vk.y;
            Ks[rr * KS_STR + 4 * d4 + 2] = vk.z;
            Ks[rr * KS_STR + 4 * d4 + 3] = vk.w;
            float4 vv = *(const float4*)(v + base);
            Vs[rr * VS_STR + 4 * d4 + 0] = vv.x;
            Vs[rr * VS_STR + 4 * d4 + 1] = vv.y;
            Vs[rr * VS_STR + 4 * d4 + 2] = vv.z;
            Vs[rr * VS_STR + 4 * d4 + 3] = vv.w;
        }
        __syncthreads();

        // S = Q K^T  (per-thread 4x8 micro-tile)
        float sc[4][8];
#pragma unroll
        for (int i = 0; i < 4; i++)
#pragma unroll
            for (int j = 0; j < 8; j++) sc[i][j] = 0.f;
#pragma unroll 4
        for (int dd = 0; dd < HD; dd++) {
            float a[4], bb[8];
#pragma unroll
            for (int i = 0; i < 4; i++) a[i] = Qs[(4 * ty + i) * QS_STR + dd];
#pragma unroll
            for (int j = 0; j < 8; j++) bb[j] = Ks[(8 * tx + j) * KS_STR + dd];
#pragma unroll
            for (int i = 0; i < 4; i++)
#pragma unroll
                for (int j = 0; j < 8; j++)
                    sc[i][j] += a[i] * bb[j];
        }

        const bool diag = (kb == qb);

        // Online softmax stats, rows reduced over 8-lane tx groups
#pragma unroll
        for (int i = 0; i < 4; i++) {
            int qg = qb * 64 + 4 * ty + i;
            float mx = -CUDART_INF_F;
#pragma unroll
            for (int j = 0; j < 8; j++) {
                float val = sc[i][j] * scale;
                if (diag && (kb * 64 + 8 * tx + j) > qg) val = -CUDART_INF_F;
                sc[i][j] = val;
                mx = fmaxf(mx, val);
            }
#pragma unroll
            for (int off = 4; off; off >>= 1)
                mx = fmaxf(mx, __shfl_xor_sync(0xffffffffu, mx, off));
            float m_new = fmaxf(m_i[i], mx);
            float alpha = __expf(m_i[i] - m_new);
            float rs = 0.f;
#pragma unroll
            for (int j = 0; j < 8; j++) {
                float p = __expf(sc[i][j] - m_new);
                Ss[(4 * ty + i) * SS_STR + 8 * tx + j] = p;
                rs += p;
            }
#pragma unroll
            for (int off = 4; off; off >>= 1)
                rs += __shfl_xor_sync(0xffffffffu, rs, off);
            l_i[i] = l_i[i] * alpha + rs;
            m_i[i] = m_new;
#pragma unroll
            for (int c = 0; c < 16; c++) acc[i][c] *= alpha;
        }
        __syncthreads();

        // O += P V   (per-thread 4 rows x 16 cols)
#pragma unroll 2
        for (int kk = 0; kk < 64; kk++) {
            float p[4];
#pragma unroll
            for (int i = 0; i < 4; i++) p[i] = Ss[(4 * ty + i) * SS_STR + kk];
            float4 v0 = *(const float4*)(Vs + kk * VS_STR + 16 * tx + 0);
            float4 v1 = *(const float4*)(Vs + kk * VS_STR + 16 * tx + 4);
            float4 v2 = *(const float4*)(Vs + kk * VS_STR + 16 * tx + 8);
            float4 v3 = *(const float4*)(Vs + kk * VS_STR + 16 * tx + 12);
            float vv[16] = {v0.x, v0.y, v0.z, v0.w, v1.x, v1.y, v1.z, v1.w,
                            v2.x, v2.y, v2.z, v2.w, v3.x, v3.y, v3.z, v3.w};
#pragma unroll
            for (int i = 0; i < 4; i++)
#pragma unroll
                for (int c = 0; c < 16; c++)
                    acc[i][c] += p[i] * vv[c];
        }
    }

    // Normalize and write O to [b, s, h, d]
#pragma unroll
    for (int i = 0; i < 4; i++) {
        float inv = 1.f / l_i[i];
        int s = qb * 64 + 4 * ty + i;
        float* op = o + ((size_t)((b * SEQ + s) * NH + h)) * HD + 16 * tx;
        float4 o0 = make_float4(acc[i][0] * inv,  acc[i][1] * inv,  acc[i][2] * inv,  acc[i][3] * inv);
        float4 o1 = make_float4(acc[i][4] * inv,  acc[i][5] * inv,  acc[i][6] * inv,  acc[i][7] * inv);
        float4 o2 = make_float4(acc[i][8] * inv,  acc[i][9] * inv,  acc[i][10] * inv, acc[i][11] * inv);
        float4 o3 = make_float4(acc[i][12] * inv, acc[i][13] * inv, acc[i][14] * inv, acc[i][15] * inv);
        *(float4*)(op + 0)  = o0;
        *(float4*)(op + 4)  = o1;
        *(float4*)(op + 8)  = o2;
        *(float4*)(op + 12) = o3;
    }
}

// ======================================================================
extern "C" void kernel_launch(void* const* d_in, const int* in_sizes, int n_in,
                              void* d_out, int out_size)
{
    const float* x  = (const float*)d_in[0];
    // d_in[1] = mask (exact causal tril; reproduced by predicate), d_in[8] = start_pos (0)
    const float* cs = (const float*)d_in[2];
    const float* sn = (const float*)d_in[3];
    const float* wq = (const float*)d_in[4];
    const float* wk = (const float*)d_in[5];
    const float* wv = (const float*)d_in[6];
    const float* wo = (const float*)d_in[7];
    float* out = (float*)d_out;

    float *q, *k, *v, *attn;
    cudaGetSymbolAddress((void**)&q,    g_q);
    cudaGetSymbolAddress((void**)&k,    g_k);
    cudaGetSymbolAddress((void**)&v,    g_v);
    cudaGetSymbolAddress((void**)&attn, g_attn);

    cudaFuncSetAttribute(attn_kernel, cudaFuncAttributeMaxDynamicSharedMemorySize, ATTN_SMEM);

    // QKV projections
    gemm_tn<<<dim3(DIM / 64,   ROWS / 128), 256>>>(x, wq, q, ROWS, DIM,   DIM);
    gemm_tn<<<dim3(KVDIM / 64, ROWS / 128), 256>>>(x, wk, k, ROWS, KVDIM, DIM);
    gemm_tn<<<dim3(KVDIM / 64, ROWS / 128), 256>>>(x, wv, v, ROWS, KVDIM, DIM);

    // RoPE on Q and K
    rope_kernel<<<(ROWS * NH  * 64) / 256, 256>>>(q, cs, sn, NH);
    rope_kernel<<<(ROWS * NKV * 64) / 256, 256>>>(k, cs, sn, NKV);

    // Causal GQA flash attention
    attn_kernel<<<dim3(SEQ / 64, NH, 2), 128, ATTN_SMEM>>>(q, k, v, attn);

    // Output projection
    gemm_tn<<<dim3(DIM / 64, ROWS / 128), 256>>>(attn, wo, out, ROWS, DIM, DIM);
}